// round 10
// baseline (speedup 1.0000x reference)
#include <cuda_runtime.h>
#include <cuda_fp16.h>
#include <stdint.h>

// RNN1DGeneral: B=16384, L=64, H=64, DEPTH=2, D_L=2, D_C=8, LPF=0.5
// R10: n-split warp pairs. Two warps share each 16-row tile; warp hw
// computes hidden cols [32hw, 32hw+32). 512-thread CTAs -> 16 warps/SM
// (4/SMSP). Per step each warp runs 48 MMAs + 24 LDS.128; the halves are
// exchanged through a per-pair SMEM buffer (D->A identity makes the own
// half free), synced by 64-thread named barriers.

__device__ __forceinline__ void mmaf16(uint32_t& d0, uint32_t& d1,
    uint32_t a0, uint32_t a1, uint32_t a2, uint32_t a3,
    uint32_t b0, uint32_t b1)
{
    asm("mma.sync.aligned.m16n8k16.row.col.f16.f16.f16.f16 "
        "{%0,%1},{%2,%3,%4,%5},{%6,%7},{%0,%1};"
        : "+r"(d0), "+r"(d1)
        : "r"(a0), "r"(a1), "r"(a2), "r"(a3), "r"(b0), "r"(b1));
}

__device__ __forceinline__ void mmaf16_init(uint32_t& d0, uint32_t& d1,
    uint32_t a0, uint32_t a1, uint32_t a2, uint32_t a3,
    uint32_t b0, uint32_t b1, uint32_t c0, uint32_t c1)
{
    asm("mma.sync.aligned.m16n8k16.row.col.f16.f16.f16.f16 "
        "{%0,%1},{%2,%3,%4,%5},{%6,%7},{%8,%9};"
        : "=r"(d0), "=r"(d1)
        : "r"(a0), "r"(a1), "r"(a2), "r"(a3), "r"(b0), "r"(b1),
          "r"(c0), "r"(c1));
}

__device__ __forceinline__ uint32_t pack2(float lo, float hi) {
    __half2 h = __floats2half2_rn(lo, hi);
    return *reinterpret_cast<const uint32_t*>(&h);
}

// elementwise ELU on packed half2: max(v,0) + min(exp(v)-1, 0)
__device__ __forceinline__ uint32_t elu_h2(uint32_t u) {
    const uint32_t LOG2E2 = 0x3DC53DC5u;
    const uint32_t ONE2   = 0x3C003C00u;
    uint32_t zero = 0u;
    uint32_t t, e, em1, mx, mn, r;
    asm("mul.rn.f16x2 %0, %1, %2;" : "=r"(t) : "r"(u), "r"(LOG2E2));
    asm("ex2.approx.f16x2 %0, %1;" : "=r"(e) : "r"(t));
    asm("sub.rn.f16x2 %0, %1, %2;" : "=r"(em1) : "r"(e), "r"(ONE2));
    asm("max.f16x2 %0, %1, %2;" : "=r"(mx) : "r"(u), "r"(zero));
    asm("min.f16x2 %0, %1, %2;" : "=r"(mn) : "r"(em1), "r"(zero));
    asm("add.rn.f16x2 %0, %1, %2;" : "=r"(r) : "r"(mx), "r"(mn));
    return r;
}

__device__ __forceinline__ void hfma2_acc(uint32_t& acc, uint32_t a, uint32_t b) {
    asm("fma.rn.f16x2 %0, %1, %2, %0;" : "+r"(acc) : "r"(a), "r"(b));
}

#define PAIR_BAR() asm volatile("bar.sync %0, %1;" :: "r"(barid), "r"(64) : "memory")

__global__ void __launch_bounds__(512, 1) rnn_fused(
    const int*   __restrict__ x,     // [16384, 65]
    const float* __restrict__ Win0,  // [2, 64]
    const float* __restrict__ Win1,  // [64, 64]
    const float* __restrict__ Wh,    // [2, 64, 64]
    const float* __restrict__ bvec,  // [2, 64]
    const float* __restrict__ Wlat,  // [64, 2]
    const float* __restrict__ blat,  // [2]
    const float* __restrict__ Wcav,  // [128, 8]
    const float* __restrict__ bcav,  // [8]
    float*       __restrict__ out)   // [16384]
{
    __shared__ uint4  sW4[3 * 4 * 4 * 32];  // weights: l 0=Wh0,1=Win1,2=Wh1 (24KB)
    __shared__ __half sX[8][16][72];        // per-pair exchange (18KB, stride 72)
    __shared__ float  sV[3][72];            // V[b]=Win0[b]+b0; V[2]=b0
    __shared__ float  sB1[64];
    __shared__ float  sWlat[64][2];
    __shared__ float  sCav[128][8];
    __shared__ float  sB[10];

    const int tid = threadIdx.x;

    for (int i = tid; i < 3 * 4 * 4 * 32; i += 512) {
        int lane_ = i & 31, ntp_ = (i >> 5) & 3, kt_ = (i >> 7) & 3, l_ = i >> 9;
        int q_ = lane_ >> 2, m_ = lane_ & 3;
        int k0 = 16 * kt_ + 2 * m_;
        int n0 = 16 * ntp_ + q_;
        int n1 = n0 + 8;
        const float* src = (l_ == 0) ? Wh : (l_ == 1 ? Win1 : (Wh + 4096));
        uint4 u;
        u.x = pack2(src[k0 * 64 + n0],       src[(k0 + 1) * 64 + n0]);
        u.y = pack2(src[(k0 + 8) * 64 + n0], src[(k0 + 9) * 64 + n0]);
        u.z = pack2(src[k0 * 64 + n1],       src[(k0 + 1) * 64 + n1]);
        u.w = pack2(src[(k0 + 8) * 64 + n1], src[(k0 + 9) * 64 + n1]);
        sW4[i] = u;
    }
    for (int i = tid; i < 128 * 8; i += 512)
        (reinterpret_cast<float*>(sCav))[i] = Wcav[i];
    if (tid < 64) {
        int c = tid;
        float b0c = bvec[c];
        sV[0][c] = Win0[c] + b0c;
        sV[1][c] = Win0[64 + c] + b0c;
        sV[2][c] = b0c;
        sB1[c] = bvec[64 + c];
        sWlat[c][0] = Wlat[2 * c];
        sWlat[c][1] = Wlat[2 * c + 1];
    }
    if (tid < 8) sB[tid] = bcav[tid];
    if (tid < 2) sB[8 + tid] = blat[tid];
    __syncthreads();

    const int lane = tid & 31, warp = tid >> 5;
    const int pair = warp >> 1, hw = warp & 1;
    const int q = lane >> 2, m = lane & 3;
    const int rowbase = blockIdx.x * 128 + pair * 16;
    const int ntbase = 4 * hw;       // this warp's n-cols: [8*ntbase, 8*ntbase+32)
    const int barid = 1 + pair;      // named barrier per pair (64 threads)
    const uint4* wp4 = sW4 + lane;

    // pack per-row input bits for BOTH row sets (MMAs cover all 16 rows)
    uint64_t xb[2];
    int xl_own = 0;
#pragma unroll
    for (int rr = 0; rr < 2; rr++) {
        int r = rowbase + q + rr * 8;
        const int* xr = x + r * 65;
        uint64_t bits = 0;
#pragma unroll 8
        for (int t = 0; t < 64; t++)
            bits |= ((uint64_t)(xr[t] & 1)) << t;
        xb[rr] = bits;
        if (rr == hw) xl_own = xr[64] & 7;
    }

    // Wlat half2 pairs, full 8 col-groups (head uses full h1 A-frags)
    uint32_t wl2[8][2];
#pragma unroll
    for (int g = 0; g < 8; g++) {
        int col = 8 * g + 2 * m;
        wl2[g][0] = pack2(sWlat[col][0], sWlat[col + 1][0]);
        wl2[g][1] = pack2(sWlat[col][1], sWlat[col + 1][1]);
    }
    const float bl0 = sB[8], bl1 = sB[9];

    // C-init constants for OWN n-half (local a = 0..3 -> nt = ntbase+a)
    uint32_t b1h[4], Vh[2][4];
#pragma unroll
    for (int a = 0; a < 4; a++) {
        int col = 8 * (ntbase + a) + 2 * m;
        b1h[a]  = pack2(sB1[col], sB1[col + 1]);
        Vh[0][a] = pack2(sV[0][col], sV[0][col + 1]);
        Vh[1][a] = pack2(sV[1][col], sV[1][col + 1]);
    }

    // FULL hidden-state A-fragments (both warps hold all k)
    // h0(0) = elu(b0) (same for all rows); h1(-1) = 0
    uint32_t h0A[4][4], h1A[4][4];
#pragma unroll
    for (int kt = 0; kt < 4; kt++) {
        int c0 = 16 * kt + 2 * m;
        uint32_t va = elu_h2(pack2(sV[2][c0], sV[2][c0 + 1]));
        uint32_t vb = elu_h2(pack2(sV[2][c0 + 8], sV[2][c0 + 9]));
        h0A[kt][0] = va; h0A[kt][1] = va;
        h0A[kt][2] = vb; h0A[kt][3] = vb;
        h1A[kt][0] = 0u; h1A[kt][1] = 0u; h1A[kt][2] = 0u; h1A[kt][3] = 0u;
    }

    float lp = 0.f;
    uint32_t d1s[4][2], d2s[4][2];

#pragma unroll 1
    for (int t = 0; t < 65; t++) {
        const bool last = (t == 64);

        // ===== MMA region (own n-half: 4 nt = 2 ntp groups) =====
        // layer1 A: d2s = b1 + h1(t-1) @ Wh1
#pragma unroll
        for (int lpi = 0; lpi < 2; lpi++) {
            uint4 u = wp4[((2 * 4 + 0) * 4 + (2 * hw + lpi)) * 32];
            mmaf16_init(d2s[2 * lpi][0], d2s[2 * lpi][1],
                h1A[0][0], h1A[0][1], h1A[0][2], h1A[0][3], u.x, u.y,
                b1h[2 * lpi], b1h[2 * lpi]);
            mmaf16_init(d2s[2 * lpi + 1][0], d2s[2 * lpi + 1][1],
                h1A[0][0], h1A[0][1], h1A[0][2], h1A[0][3], u.z, u.w,
                b1h[2 * lpi + 1], b1h[2 * lpi + 1]);
        }
#pragma unroll
        for (int kt = 1; kt < 4; kt++)
#pragma unroll
            for (int lpi = 0; lpi < 2; lpi++) {
                uint4 u = wp4[((2 * 4 + kt) * 4 + (2 * hw + lpi)) * 32];
                mmaf16(d2s[2 * lpi][0], d2s[2 * lpi][1],
                    h1A[kt][0], h1A[kt][1], h1A[kt][2], h1A[kt][3], u.x, u.y);
                mmaf16(d2s[2 * lpi + 1][0], d2s[2 * lpi + 1][1],
                    h1A[kt][0], h1A[kt][1], h1A[kt][2], h1A[kt][3], u.z, u.w);
            }

        // layer0(next): d1s = V[x_t] + h0(t) @ Wh0
        if (!last) {
            int i0 = (int)((xb[0] >> t) & 1ull);
            int i1 = (int)((xb[1] >> t) & 1ull);
#pragma unroll
            for (int lpi = 0; lpi < 2; lpi++) {
                uint4 u = wp4[((0 * 4 + 0) * 4 + (2 * hw + lpi)) * 32];
                mmaf16_init(d1s[2 * lpi][0], d1s[2 * lpi][1],
                    h0A[0][0], h0A[0][1], h0A[0][2], h0A[0][3], u.x, u.y,
                    Vh[i0][2 * lpi], Vh[i1][2 * lpi]);
                mmaf16_init(d1s[2 * lpi + 1][0], d1s[2 * lpi + 1][1],
                    h0A[0][0], h0A[0][1], h0A[0][2], h0A[0][3], u.z, u.w,
                    Vh[i0][2 * lpi + 1], Vh[i1][2 * lpi + 1]);
            }
#pragma unroll
            for (int kt = 1; kt < 4; kt++)
#pragma unroll
                for (int lpi = 0; lpi < 2; lpi++) {
                    uint4 u = wp4[((0 * 4 + kt) * 4 + (2 * hw + lpi)) * 32];
                    mmaf16(d1s[2 * lpi][0], d1s[2 * lpi][1],
                        h0A[kt][0], h0A[kt][1], h0A[kt][2], h0A[kt][3], u.x, u.y);
                    mmaf16(d1s[2 * lpi + 1][0], d1s[2 * lpi + 1][1],
                        h0A[kt][0], h0A[kt][1], h0A[kt][2], h0A[kt][3], u.z, u.w);
                }
        }

        // layer1 B: d2s += h0(t) @ Win1
#pragma unroll
        for (int kt = 0; kt < 4; kt++)
#pragma unroll
            for (int lpi = 0; lpi < 2; lpi++) {
                uint4 u = wp4[((1 * 4 + kt) * 4 + (2 * hw + lpi)) * 32];
                mmaf16(d2s[2 * lpi][0], d2s[2 * lpi][1],
                    h0A[kt][0], h0A[kt][1], h0A[kt][2], h0A[kt][3], u.x, u.y);
                mmaf16(d2s[2 * lpi + 1][0], d2s[2 * lpi + 1][1],
                    h0A[kt][0], h0A[kt][1], h0A[kt][2], h0A[kt][3], u.z, u.w);
            }

        // ===== head(t-1) for OWN row set (h = hw), from full old h1A =====
        if (t > 0) {
            uint32_t za0 = 0u, za1 = 0u;
#pragma unroll
            for (int g = 0; g < 8; g++) {
                uint32_t u = h1A[g >> 1][2 * (g & 1) + hw];
                hfma2_acc(za0, u, wl2[g][0]);
                hfma2_acc(za1, u, wl2[g][1]);
            }
            float2 f0 = __half22float2(*reinterpret_cast<__half2*>(&za0));
            float2 f1 = __half22float2(*reinterpret_cast<__half2*>(&za1));
            float z0 = f0.x + f0.y, z1 = f1.x + f1.y;
            z0 += __shfl_xor_sync(0xffffffffu, z0, 1);
            z0 += __shfl_xor_sync(0xffffffffu, z0, 2);
            z1 += __shfl_xor_sync(0xffffffffu, z1, 1);
            z1 += __shfl_xor_sync(0xffffffffu, z1, 2);
            z0 += bl0; z1 += bl1;
            int bit = (int)((xb[hw] >> (t - 1)) & 1ull);
            float mx = fmaxf(z0, z1);
            float lse = mx + __logf(1.f + __expf(-fabsf(z0 - z1)));
            float zsel = bit ? z1 : z0;
            lp += 0.5f * (zsel - lse);
        }

        // ===== h1 exchange: own half free via D->A identity =====
        {
            uint32_t e[4][2];
#pragma unroll
            for (int a = 0; a < 4; a++) {
                e[a][0] = elu_h2(d2s[a][0]);
                e[a][1] = elu_h2(d2s[a][1]);
            }
#pragma unroll
            for (int a = 0; a < 4; a++)
#pragma unroll
                for (int j = 0; j < 2; j++)
                    *reinterpret_cast<uint32_t*>(
                        &sX[pair][q + 8 * j][8 * (ntbase + a) + 2 * m]) = e[a][j];
            PAIR_BAR();
#pragma unroll
            for (int s2 = 0; s2 < 2; s2++) {
                int kt = 2 * hw + s2;           // own k-tiles from own D-frags
                h1A[kt][0] = e[2 * s2][0];
                h1A[kt][1] = e[2 * s2][1];
                h1A[kt][2] = e[2 * s2 + 1][0];
                h1A[kt][3] = e[2 * s2 + 1][1];
                int pkt = 2 * (1 - hw) + s2;    // partner k-tiles from SMEM
                int c0 = 16 * pkt + 2 * m;
                h1A[pkt][0] = *reinterpret_cast<const uint32_t*>(&sX[pair][q][c0]);
                h1A[pkt][1] = *reinterpret_cast<const uint32_t*>(&sX[pair][q + 8][c0]);
                h1A[pkt][2] = *reinterpret_cast<const uint32_t*>(&sX[pair][q][c0 + 8]);
                h1A[pkt][3] = *reinterpret_cast<const uint32_t*>(&sX[pair][q + 8][c0 + 8]);
            }
            PAIR_BAR();
        }

        // ===== h0 exchange (skip at last) =====
        if (!last) {
            uint32_t e[4][2];
#pragma unroll
            for (int a = 0; a < 4; a++) {
                e[a][0] = elu_h2(d1s[a][0]);
                e[a][1] = elu_h2(d1s[a][1]);
            }
#pragma unroll
            for (int a = 0; a < 4; a++)
#pragma unroll
                for (int j = 0; j < 2; j++)
                    *reinterpret_cast<uint32_t*>(
                        &sX[pair][q + 8 * j][8 * (ntbase + a) + 2 * m]) = e[a][j];
            PAIR_BAR();
#pragma unroll
            for (int s2 = 0; s2 < 2; s2++) {
                int kt = 2 * hw + s2;
                h0A[kt][0] = e[2 * s2][0];
                h0A[kt][1] = e[2 * s2][1];
                h0A[kt][2] = e[2 * s2 + 1][0];
                h0A[kt][3] = e[2 * s2 + 1][1];
                int pkt = 2 * (1 - hw) + s2;
                int c0 = 16 * pkt + 2 * m;
                h0A[pkt][0] = *reinterpret_cast<const uint32_t*>(&sX[pair][q][c0]);
                h0A[pkt][1] = *reinterpret_cast<const uint32_t*>(&sX[pair][q + 8][c0]);
                h0A[pkt][2] = *reinterpret_cast<const uint32_t*>(&sX[pair][q][c0 + 8]);
                h0A[pkt][3] = *reinterpret_cast<const uint32_t*>(&sX[pair][q + 8][c0 + 8]);
            }
            PAIR_BAR();
        }
    }
    // after loop: h0A = h0(64), h1A = h1(64)  (full, in both warps)

    // ===== cavity head for OWN row set (h = hw) =====
    {
        float zc[8];
#pragma unroll
        for (int c = 0; c < 8; c++) zc[c] = 0.f;
#pragma unroll
        for (int kt = 0; kt < 4; kt++)
#pragma unroll
            for (int p = 0; p < 2; p++) {
                int col = 16 * kt + 8 * p + 2 * m;
                __half2 ha = *reinterpret_cast<const __half2*>(&h0A[kt][2 * p + hw]);
                __half2 hb = *reinterpret_cast<const __half2*>(&h1A[kt][2 * p + hw]);
                float v0 = __half2float(__low2half(ha));
                float v1 = __half2float(__high2half(ha));
                float w0 = __half2float(__low2half(hb));
                float w1 = __half2float(__high2half(hb));
#pragma unroll
                for (int c = 0; c < 8; c++) {
                    zc[c] += v0 * sCav[col][c] + v1 * sCav[col + 1][c]
                           + w0 * sCav[64 + col][c] + w1 * sCav[64 + col + 1][c];
                }
            }
#pragma unroll
        for (int c = 0; c < 8; c++) {
            zc[c] += __shfl_xor_sync(0xffffffffu, zc[c], 1);
            zc[c] += __shfl_xor_sync(0xffffffffu, zc[c], 2);
            zc[c] += sB[c];
        }
        float mx = zc[0];
#pragma unroll
        for (int c = 1; c < 8; c++) mx = fmaxf(mx, zc[c]);
        float s = 0.f;
#pragma unroll
        for (int c = 0; c < 8; c++) s += __expf(zc[c] - mx);
        float lse = mx + __logf(s);
        float zsel = zc[0];
#pragma unroll
        for (int c = 1; c < 8; c++) if (xl_own == c) zsel = zc[c];
        float total = lp + 0.5f * (zsel - lse);
        if (m == 0)
            out[rowbase + q + 8 * hw] = total;
    }
}

extern "C" void kernel_launch(void* const* d_in, const int* in_sizes, int n_in,
                              void* d_out, int out_size) {
    (void)in_sizes; (void)n_in; (void)out_size;
    const int*   x    = (const int*)d_in[0];
    const float* Win0 = (const float*)d_in[1];
    const float* Win1 = (const float*)d_in[2];
    const float* Wh   = (const float*)d_in[3];
    const float* b    = (const float*)d_in[4];
    const float* Wlat = (const float*)d_in[5];
    const float* blat = (const float*)d_in[6];
    const float* Wcav = (const float*)d_in[7];
    const float* bcav = (const float*)d_in[8];
    float* out = (float*)d_out;
    rnn_fused<<<128, 512>>>(x, Win0, Win1, Wh, b, Wlat, blat, Wcav, bcav, out);
}

// round 11
// speedup vs baseline: 1.0142x; 1.0142x over previous
#include <cuda_runtime.h>
#include <cuda_fp16.h>
#include <stdint.h>

// RNN1DGeneral: B=16384, L=64, H=64, DEPTH=2, D_L=2, D_C=8, LPF=0.5
// R11: n-split warp pairs, repaired. 512 thr/CTA (16 warps, 8 pairs), each
// warp owns hidden cols [32hw,32hw+32) of a 16-row tile. Fits the 128-reg
// cap (wl2/Vh tables in SMEM), ONE named barrier per step via a
// double-buffered exchange, dynamic SMEM (~101KB).

__device__ __forceinline__ void mmaf16(uint32_t& d0, uint32_t& d1,
    uint32_t a0, uint32_t a1, uint32_t a2, uint32_t a3,
    uint32_t b0, uint32_t b1)
{
    asm("mma.sync.aligned.m16n8k16.row.col.f16.f16.f16.f16 "
        "{%0,%1},{%2,%3,%4,%5},{%6,%7},{%0,%1};"
        : "+r"(d0), "+r"(d1)
        : "r"(a0), "r"(a1), "r"(a2), "r"(a3), "r"(b0), "r"(b1));
}

__device__ __forceinline__ void mmaf16_init(uint32_t& d0, uint32_t& d1,
    uint32_t a0, uint32_t a1, uint32_t a2, uint32_t a3,
    uint32_t b0, uint32_t b1, uint32_t c0, uint32_t c1)
{
    asm("mma.sync.aligned.m16n8k16.row.col.f16.f16.f16.f16 "
        "{%0,%1},{%2,%3,%4,%5},{%6,%7},{%8,%9};"
        : "=r"(d0), "=r"(d1)
        : "r"(a0), "r"(a1), "r"(a2), "r"(a3), "r"(b0), "r"(b1),
          "r"(c0), "r"(c1));
}

__device__ __forceinline__ uint32_t pack2(float lo, float hi) {
    __half2 h = __floats2half2_rn(lo, hi);
    return *reinterpret_cast<const uint32_t*>(&h);
}

__device__ __forceinline__ uint32_t elu_h2(uint32_t u) {
    const uint32_t LOG2E2 = 0x3DC53DC5u;
    const uint32_t ONE2   = 0x3C003C00u;
    uint32_t zero = 0u;
    uint32_t t, e, em1, mx, mn, r;
    asm("mul.rn.f16x2 %0, %1, %2;" : "=r"(t) : "r"(u), "r"(LOG2E2));
    asm("ex2.approx.f16x2 %0, %1;" : "=r"(e) : "r"(t));
    asm("sub.rn.f16x2 %0, %1, %2;" : "=r"(em1) : "r"(e), "r"(ONE2));
    asm("max.f16x2 %0, %1, %2;" : "=r"(mx) : "r"(u), "r"(zero));
    asm("min.f16x2 %0, %1, %2;" : "=r"(mn) : "r"(em1), "r"(zero));
    asm("add.rn.f16x2 %0, %1, %2;" : "=r"(r) : "r"(mx), "r"(mn));
    return r;
}

__device__ __forceinline__ void hfma2_acc(uint32_t& acc, uint32_t a, uint32_t b) {
    asm("fma.rn.f16x2 %0, %1, %2, %0;" : "+r"(acc) : "r"(a), "r"(b));
}

#define PAIR_BAR() asm volatile("bar.sync %0, %1;" :: "r"(barid), "r"(64) : "memory")

// dynamic SMEM layout (bytes):
//   [0      , 24576) sW4   : uint4[3*4*4*32]      weights (l 0=Wh0,1=Win1,2=Wh1)
//   [24576  , 98304) sX    : half[2][8][2][16][72] dbl-buffered exchange
//   [98304  , 98736) sVh   : u32[3][36]           pack2(V[i][8nt+2m], +1) at [i*36+4nt+m]
//   [98736  , 98992) sWl2  : uint2[32]            Wlat pairs at [4g+m]
//   [98992  ,103088) sCav  : float[128][8]
//   [103088 ,103128) sB    : float[10]            bcav, blat
//   [103128 ,103256) sB1h  : u32[32]              pack2(b1[8g+2m], +1) at [4g+m]
#define SMEM_BYTES 103424

__global__ void __launch_bounds__(512, 1) rnn_fused(
    const int*   __restrict__ x,     // [16384, 65]
    const float* __restrict__ Win0,  // [2, 64]
    const float* __restrict__ Win1,  // [64, 64]
    const float* __restrict__ Wh,    // [2, 64, 64]
    const float* __restrict__ bvec,  // [2, 64]
    const float* __restrict__ Wlat,  // [64, 2]
    const float* __restrict__ blat,  // [2]
    const float* __restrict__ Wcav,  // [128, 8]
    const float* __restrict__ bcav,  // [8]
    float*       __restrict__ out)   // [16384]
{
    extern __shared__ char smraw[];
    uint4*    sW4  = reinterpret_cast<uint4*>(smraw);
    __half*   sX   = reinterpret_cast<__half*>(smraw + 24576);
    uint32_t* sVh  = reinterpret_cast<uint32_t*>(smraw + 98304);
    uint2*    sWl2 = reinterpret_cast<uint2*>(smraw + 98736);
    float*    sCav = reinterpret_cast<float*>(smraw + 98992);
    float*    sB   = reinterpret_cast<float*>(smraw + 103088);
    uint32_t* sB1h = reinterpret_cast<uint32_t*>(smraw + 103128);

    const int tid = threadIdx.x;

    for (int i = tid; i < 3 * 4 * 4 * 32; i += 512) {
        int lane_ = i & 31, ntp_ = (i >> 5) & 3, kt_ = (i >> 7) & 3, l_ = i >> 9;
        int q_ = lane_ >> 2, m_ = lane_ & 3;
        int k0 = 16 * kt_ + 2 * m_;
        int n0 = 16 * ntp_ + q_;
        int n1 = n0 + 8;
        const float* src = (l_ == 0) ? Wh : (l_ == 1 ? Win1 : (Wh + 4096));
        uint4 u;
        u.x = pack2(src[k0 * 64 + n0],       src[(k0 + 1) * 64 + n0]);
        u.y = pack2(src[(k0 + 8) * 64 + n0], src[(k0 + 9) * 64 + n0]);
        u.z = pack2(src[k0 * 64 + n1],       src[(k0 + 1) * 64 + n1]);
        u.w = pack2(src[(k0 + 8) * 64 + n1], src[(k0 + 9) * 64 + n1]);
        sW4[i] = u;
    }
    for (int i = tid; i < 128 * 8; i += 512)
        sCav[i] = Wcav[i];
    if (tid < 96) {
        int i = tid >> 5, idx = tid & 31;
        int nt_ = idx >> 2, mm = idx & 3;
        int c = 8 * nt_ + 2 * mm;
        float lo, hi;
        if (i == 2) { lo = bvec[c]; hi = bvec[c + 1]; }
        else { lo = Win0[64 * i + c] + bvec[c]; hi = Win0[64 * i + c + 1] + bvec[c + 1]; }
        sVh[i * 36 + idx] = pack2(lo, hi);
    }
    if (tid < 32) {
        int g = tid >> 2, mm = tid & 3;
        int col = 8 * g + 2 * mm;
        uint2 w;
        w.x = pack2(Wlat[2 * col],     Wlat[2 * col + 2]);
        w.y = pack2(Wlat[2 * col + 1], Wlat[2 * col + 3]);
        sWl2[tid] = w;
        sB1h[tid] = pack2(bvec[64 + col], bvec[64 + col + 1]);
    }
    if (tid < 8) sB[tid] = bcav[tid];
    if (tid < 2) sB[8 + tid] = blat[tid];
    __syncthreads();

    const int lane = tid & 31, warp = tid >> 5;
    const int pair = warp >> 1, hw = warp & 1;
    const int q = lane >> 2, m = lane & 3;
    const int rowbase = blockIdx.x * 128 + pair * 16;
    const int ntbase = 4 * hw;
    const int barid = 1 + pair;
    const uint4* wp4 = sW4 + lane;

#define XIDX(buf, layer, row, col) \
    (((((buf) * 8 + pair) * 2 + (layer)) * 16 + (row)) * 72 + (col))

    // pack per-row input bits for BOTH row sets
    uint64_t xb[2];
    int xl_own = 0;
#pragma unroll
    for (int rr = 0; rr < 2; rr++) {
        int r = rowbase + q + rr * 8;
        const int* xr = x + r * 65;
        uint64_t bits = 0;
#pragma unroll 8
        for (int t = 0; t < 64; t++)
            bits |= ((uint64_t)(xr[t] & 1)) << t;
        xb[rr] = bits;
        if (rr == hw) xl_own = xr[64] & 7;
    }

    const float bl0 = sB[8], bl1 = sB[9];

    // b1 C-inits for own half (4 regs)
    uint32_t b1h[4];
#pragma unroll
    for (int a = 0; a < 4; a++)
        b1h[a] = sB1h[4 * (ntbase + a) + m];

    // full hidden-state A-fragments; h0(0)=elu(b0), h1(-1)=0
    uint32_t h0A[4][4], h1A[4][4];
#pragma unroll
    for (int kt = 0; kt < 4; kt++) {
        uint32_t va = elu_h2(sVh[2 * 36 + 4 * (2 * kt) + m]);
        uint32_t vb = elu_h2(sVh[2 * 36 + 4 * (2 * kt + 1) + m]);
        h0A[kt][0] = va; h0A[kt][1] = va;
        h0A[kt][2] = vb; h0A[kt][3] = vb;
        h1A[kt][0] = 0u; h1A[kt][1] = 0u; h1A[kt][2] = 0u; h1A[kt][3] = 0u;
    }

    float lp = 0.f;
    uint32_t d1s[4][2], d2s[4][2];

#pragma unroll 1
    for (int t = 0; t < 65; t++) {
        const bool last = (t == 64);
        const int buf = t & 1;

        // ===== MMA region (own n-half) =====
        // layer1 A: d2s = b1 + h1(t-1)@Wh1
#pragma unroll
        for (int lpi = 0; lpi < 2; lpi++) {
            uint4 u = wp4[((2 * 4 + 0) * 4 + (2 * hw + lpi)) * 32];
            mmaf16_init(d2s[2 * lpi][0], d2s[2 * lpi][1],
                h1A[0][0], h1A[0][1], h1A[0][2], h1A[0][3], u.x, u.y,
                b1h[2 * lpi], b1h[2 * lpi]);
            mmaf16_init(d2s[2 * lpi + 1][0], d2s[2 * lpi + 1][1],
                h1A[0][0], h1A[0][1], h1A[0][2], h1A[0][3], u.z, u.w,
                b1h[2 * lpi + 1], b1h[2 * lpi + 1]);
        }
#pragma unroll
        for (int kt = 1; kt < 4; kt++)
#pragma unroll
            for (int lpi = 0; lpi < 2; lpi++) {
                uint4 u = wp4[((2 * 4 + kt) * 4 + (2 * hw + lpi)) * 32];
                mmaf16(d2s[2 * lpi][0], d2s[2 * lpi][1],
                    h1A[kt][0], h1A[kt][1], h1A[kt][2], h1A[kt][3], u.x, u.y);
                mmaf16(d2s[2 * lpi + 1][0], d2s[2 * lpi + 1][1],
                    h1A[kt][0], h1A[kt][1], h1A[kt][2], h1A[kt][3], u.z, u.w);
            }

        // layer0(next): d1s = V[x_t] + h0(t)@Wh0  (C from SMEM table)
        if (!last) {
            int i0 = (int)((xb[0] >> t) & 1ull);
            int i1 = (int)((xb[1] >> t) & 1ull);
#pragma unroll
            for (int lpi = 0; lpi < 2; lpi++) {
                uint4 u = wp4[((0 * 4 + 0) * 4 + (2 * hw + lpi)) * 32];
                int a0i = 2 * lpi, a1i = 2 * lpi + 1;
                uint32_t ca0 = sVh[i0 * 36 + 4 * (ntbase + a0i) + m];
                uint32_t cb0 = sVh[i1 * 36 + 4 * (ntbase + a0i) + m];
                uint32_t ca1 = sVh[i0 * 36 + 4 * (ntbase + a1i) + m];
                uint32_t cb1 = sVh[i1 * 36 + 4 * (ntbase + a1i) + m];
                mmaf16_init(d1s[a0i][0], d1s[a0i][1],
                    h0A[0][0], h0A[0][1], h0A[0][2], h0A[0][3], u.x, u.y,
                    ca0, cb0);
                mmaf16_init(d1s[a1i][0], d1s[a1i][1],
                    h0A[0][0], h0A[0][1], h0A[0][2], h0A[0][3], u.z, u.w,
                    ca1, cb1);
            }
#pragma unroll
            for (int kt = 1; kt < 4; kt++)
#pragma unroll
                for (int lpi = 0; lpi < 2; lpi++) {
                    uint4 u = wp4[((0 * 4 + kt) * 4 + (2 * hw + lpi)) * 32];
                    mmaf16(d1s[2 * lpi][0], d1s[2 * lpi][1],
                        h0A[kt][0], h0A[kt][1], h0A[kt][2], h0A[kt][3], u.x, u.y);
                    mmaf16(d1s[2 * lpi + 1][0], d1s[2 * lpi + 1][1],
                        h0A[kt][0], h0A[kt][1], h0A[kt][2], h0A[kt][3], u.z, u.w);
                }
        }

        // layer1 B: d2s += h0(t)@Win1
#pragma unroll
        for (int kt = 0; kt < 4; kt++)
#pragma unroll
            for (int lpi = 0; lpi < 2; lpi++) {
                uint4 u = wp4[((1 * 4 + kt) * 4 + (2 * hw + lpi)) * 32];
                mmaf16(d2s[2 * lpi][0], d2s[2 * lpi][1],
                    h0A[kt][0], h0A[kt][1], h0A[kt][2], h0A[kt][3], u.x, u.y);
                mmaf16(d2s[2 * lpi + 1][0], d2s[2 * lpi + 1][1],
                    h0A[kt][0], h0A[kt][1], h0A[kt][2], h0A[kt][3], u.z, u.w);
            }

        // ===== head(t-1) for own row set from full OLD h1A =====
        if (t > 0) {
            uint32_t za0 = 0u, za1 = 0u;
#pragma unroll
            for (int g = 0; g < 8; g++) {
                uint32_t u = h1A[g >> 1][2 * (g & 1) + hw];
                uint2 w = sWl2[4 * g + m];
                hfma2_acc(za0, u, w.x);
                hfma2_acc(za1, u, w.y);
            }
            float2 f0 = __half22float2(*reinterpret_cast<__half2*>(&za0));
            float2 f1 = __half22float2(*reinterpret_cast<__half2*>(&za1));
            float z0 = f0.x + f0.y, z1 = f1.x + f1.y;
            z0 += __shfl_xor_sync(0xffffffffu, z0, 1);
            z0 += __shfl_xor_sync(0xffffffffu, z0, 2);
            z1 += __shfl_xor_sync(0xffffffffu, z1, 1);
            z1 += __shfl_xor_sync(0xffffffffu, z1, 2);
            z0 += bl0; z1 += bl1;
            int bit = (int)((xb[hw] >> (t - 1)) & 1ull);
            float mx = fmaxf(z0, z1);
            float lse = mx + __logf(1.f + __expf(-fabsf(z0 - z1)));
            float zsel = bit ? z1 : z0;
            lp += 0.5f * (zsel - lse);
        }

        // ===== ELU + single-barrier double-buffered exchange =====
        uint32_t e2[4][2], e1[4][2];
#pragma unroll
        for (int a = 0; a < 4; a++) {
            e2[a][0] = elu_h2(d2s[a][0]);
            e2[a][1] = elu_h2(d2s[a][1]);
        }
#pragma unroll
        for (int a = 0; a < 4; a++)
#pragma unroll
            for (int j = 0; j < 2; j++)
                *reinterpret_cast<uint32_t*>(
                    &sX[XIDX(buf, 0, q + 8 * j, 8 * (ntbase + a) + 2 * m)]) = e2[a][j];
        if (!last) {
#pragma unroll
            for (int a = 0; a < 4; a++) {
                e1[a][0] = elu_h2(d1s[a][0]);
                e1[a][1] = elu_h2(d1s[a][1]);
            }
#pragma unroll
            for (int a = 0; a < 4; a++)
#pragma unroll
                for (int j = 0; j < 2; j++)
                    *reinterpret_cast<uint32_t*>(
                        &sX[XIDX(buf, 1, q + 8 * j, 8 * (ntbase + a) + 2 * m)]) = e1[a][j];
        }
        PAIR_BAR();
#pragma unroll
        for (int s2 = 0; s2 < 2; s2++) {
            int kt = 2 * hw + s2;
            h1A[kt][0] = e2[2 * s2][0];
            h1A[kt][1] = e2[2 * s2][1];
            h1A[kt][2] = e2[2 * s2 + 1][0];
            h1A[kt][3] = e2[2 * s2 + 1][1];
            int pkt = 2 * (1 - hw) + s2;
            int c0 = 16 * pkt + 2 * m;
            h1A[pkt][0] = *reinterpret_cast<const uint32_t*>(&sX[XIDX(buf, 0, q, c0)]);
            h1A[pkt][1] = *reinterpret_cast<const uint32_t*>(&sX[XIDX(buf, 0, q + 8, c0)]);
            h1A[pkt][2] = *reinterpret_cast<const uint32_t*>(&sX[XIDX(buf, 0, q, c0 + 8)]);
            h1A[pkt][3] = *reinterpret_cast<const uint32_t*>(&sX[XIDX(buf, 0, q + 8, c0 + 8)]);
        }
        if (!last) {
#pragma unroll
            for (int s2 = 0; s2 < 2; s2++) {
                int kt = 2 * hw + s2;
                h0A[kt][0] = e1[2 * s2][0];
                h0A[kt][1] = e1[2 * s2][1];
                h0A[kt][2] = e1[2 * s2 + 1][0];
                h0A[kt][3] = e1[2 * s2 + 1][1];
                int pkt = 2 * (1 - hw) + s2;
                int c0 = 16 * pkt + 2 * m;
                h0A[pkt][0] = *reinterpret_cast<const uint32_t*>(&sX[XIDX(buf, 1, q, c0)]);
                h0A[pkt][1] = *reinterpret_cast<const uint32_t*>(&sX[XIDX(buf, 1, q + 8, c0)]);
                h0A[pkt][2] = *reinterpret_cast<const uint32_t*>(&sX[XIDX(buf, 1, q, c0 + 8)]);
                h0A[pkt][3] = *reinterpret_cast<const uint32_t*>(&sX[XIDX(buf, 1, q + 8, c0 + 8)]);
            }
        }
    }
    // h0A = h0(64), h1A = h1(64), full, in both warps

    // ===== cavity head for own row set =====
    {
        float zc[8];
#pragma unroll
        for (int c = 0; c < 8; c++) zc[c] = 0.f;
#pragma unroll
        for (int kt = 0; kt < 4; kt++)
#pragma unroll
            for (int p = 0; p < 2; p++) {
                int col = 16 * kt + 8 * p + 2 * m;
                __half2 ha = *reinterpret_cast<const __half2*>(&h0A[kt][2 * p + hw]);
                __half2 hb = *reinterpret_cast<const __half2*>(&h1A[kt][2 * p + hw]);
                float v0 = __half2float(__low2half(ha));
                float v1 = __half2float(__high2half(ha));
                float w0 = __half2float(__low2half(hb));
                float w1 = __half2float(__high2half(hb));
#pragma unroll
                for (int c = 0; c < 8; c++) {
                    zc[c] += v0 * sCav[col * 8 + c] + v1 * sCav[(col + 1) * 8 + c]
                           + w0 * sCav[(64 + col) * 8 + c] + w1 * sCav[(64 + col + 1) * 8 + c];
                }
            }
#pragma unroll
        for (int c = 0; c < 8; c++) {
            zc[c] += __shfl_xor_sync(0xffffffffu, zc[c], 1);
            zc[c] += __shfl_xor_sync(0xffffffffu, zc[c], 2);
            zc[c] += sB[c];
        }
        float mx = zc[0];
#pragma unroll
        for (int c = 1; c < 8; c++) mx = fmaxf(mx, zc[c]);
        float s = 0.f;
#pragma unroll
        for (int c = 0; c < 8; c++) s += __expf(zc[c] - mx);
        float lse = mx + __logf(s);
        float zsel = zc[0];
#pragma unroll
        for (int c = 1; c < 8; c++) if (xl_own == c) zsel = zc[c];
        float total = lp + 0.5f * (zsel - lse);
        if (m == 0)
            out[rowbase + q + 8 * hw] = total;
    }
}

extern "C" void kernel_launch(void* const* d_in, const int* in_sizes, int n_in,
                              void* d_out, int out_size) {
    (void)in_sizes; (void)n_in; (void)out_size;
    const int*   x    = (const int*)d_in[0];
    const float* Win0 = (const float*)d_in[1];
    const float* Win1 = (const float*)d_in[2];
    const float* Wh   = (const float*)d_in[3];
    const float* b    = (const float*)d_in[4];
    const float* Wlat = (const float*)d_in[5];
    const float* blat = (const float*)d_in[6];
    const float* Wcav = (const float*)d_in[7];
    const float* bcav = (const float*)d_in[8];
    float* out = (float*)d_out;
    cudaFuncSetAttribute(rnn_fused,
                         cudaFuncAttributeMaxDynamicSharedMemorySize, SMEM_BYTES);
    rnn_fused<<<128, 512, SMEM_BYTES>>>(x, Win0, Win1, Wh, b, Wlat, blat,
                                        Wcav, bcav, out);
}

// round 12
// speedup vs baseline: 1.0978x; 1.0824x over previous
#include <cuda_runtime.h>
#include <cuda_fp16.h>
#include <stdint.h>

// RNN1DGeneral: B=16384, L=64, H=64, DEPTH=2, D_L=2, D_C=8, LPF=0.5
// R12: dual-stream warps. Each warp owns TWO independent 16-row tiles,
// interleaved at every MMA so one LDS.128 weight fragment feeds two MMAs.
// grid=128 x block=128 (4 warps/SM): half the SMEM crossbar traffic of R9
// and ~2x the per-SMSP ILP. No barriers, no exchange.

__device__ __forceinline__ void mmaf16(uint32_t& d0, uint32_t& d1,
    uint32_t a0, uint32_t a1, uint32_t a2, uint32_t a3,
    uint32_t b0, uint32_t b1)
{
    asm("mma.sync.aligned.m16n8k16.row.col.f16.f16.f16.f16 "
        "{%0,%1},{%2,%3,%4,%5},{%6,%7},{%0,%1};"
        : "+r"(d0), "+r"(d1)
        : "r"(a0), "r"(a1), "r"(a2), "r"(a3), "r"(b0), "r"(b1));
}

__device__ __forceinline__ void mmaf16_init(uint32_t& d0, uint32_t& d1,
    uint32_t a0, uint32_t a1, uint32_t a2, uint32_t a3,
    uint32_t b0, uint32_t b1, uint32_t c0, uint32_t c1)
{
    asm("mma.sync.aligned.m16n8k16.row.col.f16.f16.f16.f16 "
        "{%0,%1},{%2,%3,%4,%5},{%6,%7},{%8,%9};"
        : "=r"(d0), "=r"(d1)
        : "r"(a0), "r"(a1), "r"(a2), "r"(a3), "r"(b0), "r"(b1),
          "r"(c0), "r"(c1));
}

__device__ __forceinline__ uint32_t pack2(float lo, float hi) {
    __half2 h = __floats2half2_rn(lo, hi);
    return *reinterpret_cast<const uint32_t*>(&h);
}

__device__ __forceinline__ uint32_t elu_h2(uint32_t u) {
    const uint32_t LOG2E2 = 0x3DC53DC5u;
    const uint32_t ONE2   = 0x3C003C00u;
    uint32_t zero = 0u;
    uint32_t t, e, em1, mx, mn, r;
    asm("mul.rn.f16x2 %0, %1, %2;" : "=r"(t) : "r"(u), "r"(LOG2E2));
    asm("ex2.approx.f16x2 %0, %1;" : "=r"(e) : "r"(t));
    asm("sub.rn.f16x2 %0, %1, %2;" : "=r"(em1) : "r"(e), "r"(ONE2));
    asm("max.f16x2 %0, %1, %2;" : "=r"(mx) : "r"(u), "r"(zero));
    asm("min.f16x2 %0, %1, %2;" : "=r"(mn) : "r"(em1), "r"(zero));
    asm("add.rn.f16x2 %0, %1, %2;" : "=r"(r) : "r"(mx), "r"(mn));
    return r;
}

__device__ __forceinline__ void hfma2_acc(uint32_t& acc, uint32_t a, uint32_t b) {
    asm("fma.rn.f16x2 %0, %1, %2, %0;" : "+r"(acc) : "r"(a), "r"(b));
}

__global__ void __launch_bounds__(128, 1) rnn_fused(
    const int*   __restrict__ x,     // [16384, 65]
    const float* __restrict__ Win0,  // [2, 64]
    const float* __restrict__ Win1,  // [64, 64]
    const float* __restrict__ Wh,    // [2, 64, 64]
    const float* __restrict__ bvec,  // [2, 64]
    const float* __restrict__ Wlat,  // [64, 2]
    const float* __restrict__ blat,  // [2]
    const float* __restrict__ Wcav,  // [128, 8]
    const float* __restrict__ bcav,  // [8]
    float*       __restrict__ out)   // [16384]
{
    // B-fragment quads (LDS.128): sW4[((l*4+kt)*4+ntp)*32 + lane]
    __shared__ uint4    sW4[3 * 4 * 4 * 32];  // l: 0=Wh0, 1=Win1, 2=Wh1 (24 KB)
    __shared__ uint32_t sVh[3 * 36];          // pack2(V[i][8nt+2m],+1) at i*36+4nt+m
    __shared__ float    sB1[64];              // b1
    __shared__ float    sWlat[64][2];
    __shared__ float    sCav[128][8];
    __shared__ float    sB[10];               // [0..7]=bcav, [8..9]=blat

    const int tid = threadIdx.x;

    for (int i = tid; i < 3 * 4 * 4 * 32; i += 128) {
        int lane_ = i & 31, ntp_ = (i >> 5) & 3, kt_ = (i >> 7) & 3, l_ = i >> 9;
        int q_ = lane_ >> 2, m_ = lane_ & 3;
        int k0 = 16 * kt_ + 2 * m_;
        int n0 = 16 * ntp_ + q_;
        int n1 = n0 + 8;
        const float* src = (l_ == 0) ? Wh : (l_ == 1 ? Win1 : (Wh + 4096));
        uint4 u;
        u.x = pack2(src[k0 * 64 + n0],       src[(k0 + 1) * 64 + n0]);
        u.y = pack2(src[(k0 + 8) * 64 + n0], src[(k0 + 9) * 64 + n0]);
        u.z = pack2(src[k0 * 64 + n1],       src[(k0 + 1) * 64 + n1]);
        u.w = pack2(src[(k0 + 8) * 64 + n1], src[(k0 + 9) * 64 + n1]);
        sW4[i] = u;
    }
    for (int i = tid; i < 128 * 8; i += 128)
        (reinterpret_cast<float*>(sCav))[i] = Wcav[i];
    if (tid < 96) {
        int i = tid >> 5, idx = tid & 31;
        int nt_ = idx >> 2, mm = idx & 3;
        int c = 8 * nt_ + 2 * mm;
        float lo, hi;
        if (i == 2) { lo = bvec[c]; hi = bvec[c + 1]; }
        else { lo = Win0[64 * i + c] + bvec[c]; hi = Win0[64 * i + c + 1] + bvec[c + 1]; }
        sVh[i * 36 + idx] = pack2(lo, hi);
    }
    if (tid < 64) {
        sB1[tid] = bvec[64 + tid];
        sWlat[tid][0] = Wlat[2 * tid];
        sWlat[tid][1] = Wlat[2 * tid + 1];
    }
    if (tid < 8) sB[tid] = bcav[tid];
    if (tid < 2) sB[8 + tid] = blat[tid];
    __syncthreads();

    const int lane = tid & 31, warp = tid >> 5;
    const int q = lane >> 2, m = lane & 3;
    const int rowbase = blockIdx.x * 128 + warp * 32;  // 2 tiles of 16 rows
    const uint4* wp4 = sW4 + lane;

    // input bits: stream s, half h -> row = rowbase + 16*s + q + 8*h
    uint64_t xb[2][2];
    int xl[2][2];
#pragma unroll
    for (int s = 0; s < 2; s++)
#pragma unroll
        for (int h = 0; h < 2; h++) {
            int r = rowbase + 16 * s + q + 8 * h;
            const int* xr = x + r * 65;
            uint64_t bits = 0;
#pragma unroll 8
            for (int t = 0; t < 64; t++)
                bits |= ((uint64_t)(xr[t] & 1)) << t;
            xb[s][h] = bits;
            xl[s][h] = xr[64] & 7;
        }

    // Wlat pairs + b1 C-inits (stream-independent)
    uint32_t wl2[8][2], b1h[8];
#pragma unroll
    for (int nt = 0; nt < 8; nt++) {
        int col = 8 * nt + 2 * m;
        wl2[nt][0] = pack2(sWlat[col][0], sWlat[col + 1][0]);
        wl2[nt][1] = pack2(sWlat[col][1], sWlat[col + 1][1]);
        b1h[nt]   = pack2(sB1[col], sB1[col + 1]);
    }
    const float bl0 = sB[8], bl1 = sB[9];

    // per-stream hidden state (packed post-ELU half2); h*(s)[nt][j]
    uint32_t h0d[2][8][2], h1d[2][8][2];
#pragma unroll
    for (int nt = 0; nt < 8; nt++) {
        uint32_t v = elu_h2(sVh[2 * 36 + 4 * nt + m]);  // h0(0) = elu(b0)
#pragma unroll
        for (int s = 0; s < 2; s++) {
            h0d[s][nt][0] = v; h0d[s][nt][1] = v;
            h1d[s][nt][0] = 0u; h1d[s][nt][1] = 0u;
        }
    }

    float lp[2][2] = {{0.f, 0.f}, {0.f, 0.f}};
    uint32_t d1s[2][8][2], d2s[2][8][2];

#pragma unroll 1
    for (int t = 0; t < 65; t++) {
        const bool last = (t == 64);

        // ===== layer1 A: d2 = b1 + h1(t-1) @ Wh1  (one load, two streams) =====
#pragma unroll
        for (int ntp = 0; ntp < 4; ntp++) {
            uint4 u = wp4[((2 * 4 + 0) * 4 + ntp) * 32];
#pragma unroll
            for (int s = 0; s < 2; s++) {
                mmaf16_init(d2s[s][2 * ntp][0], d2s[s][2 * ntp][1],
                    h1d[s][0][0], h1d[s][0][1], h1d[s][1][0], h1d[s][1][1],
                    u.x, u.y, b1h[2 * ntp], b1h[2 * ntp]);
                mmaf16_init(d2s[s][2 * ntp + 1][0], d2s[s][2 * ntp + 1][1],
                    h1d[s][0][0], h1d[s][0][1], h1d[s][1][0], h1d[s][1][1],
                    u.z, u.w, b1h[2 * ntp + 1], b1h[2 * ntp + 1]);
            }
        }
#pragma unroll
        for (int kt = 1; kt < 4; kt++)
#pragma unroll
            for (int ntp = 0; ntp < 4; ntp++) {
                uint4 u = wp4[((2 * 4 + kt) * 4 + ntp) * 32];
#pragma unroll
                for (int s = 0; s < 2; s++) {
                    mmaf16(d2s[s][2 * ntp][0], d2s[s][2 * ntp][1],
                        h1d[s][2 * kt][0], h1d[s][2 * kt][1],
                        h1d[s][2 * kt + 1][0], h1d[s][2 * kt + 1][1], u.x, u.y);
                    mmaf16(d2s[s][2 * ntp + 1][0], d2s[s][2 * ntp + 1][1],
                        h1d[s][2 * kt][0], h1d[s][2 * kt][1],
                        h1d[s][2 * kt + 1][0], h1d[s][2 * kt + 1][1], u.z, u.w);
                }
            }

        // ===== layer0(next): d1 = V[x_t] + h0(t) @ Wh0 =====
        if (!last) {
            int i0[2], i1[2];
#pragma unroll
            for (int s = 0; s < 2; s++) {
                i0[s] = (int)((xb[s][0] >> t) & 1ull);
                i1[s] = (int)((xb[s][1] >> t) & 1ull);
            }
#pragma unroll
            for (int ntp = 0; ntp < 4; ntp++) {
                uint4 u = wp4[((0 * 4 + 0) * 4 + ntp) * 32];
#pragma unroll
                for (int s = 0; s < 2; s++) {
                    int a0i = 2 * ntp, a1i = 2 * ntp + 1;
                    uint32_t ca0 = sVh[i0[s] * 36 + 4 * a0i + m];
                    uint32_t cb0 = sVh[i1[s] * 36 + 4 * a0i + m];
                    uint32_t ca1 = sVh[i0[s] * 36 + 4 * a1i + m];
                    uint32_t cb1 = sVh[i1[s] * 36 + 4 * a1i + m];
                    mmaf16_init(d1s[s][a0i][0], d1s[s][a0i][1],
                        h0d[s][0][0], h0d[s][0][1], h0d[s][1][0], h0d[s][1][1],
                        u.x, u.y, ca0, cb0);
                    mmaf16_init(d1s[s][a1i][0], d1s[s][a1i][1],
                        h0d[s][0][0], h0d[s][0][1], h0d[s][1][0], h0d[s][1][1],
                        u.z, u.w, ca1, cb1);
                }
            }
#pragma unroll
            for (int kt = 1; kt < 4; kt++)
#pragma unroll
                for (int ntp = 0; ntp < 4; ntp++) {
                    uint4 u = wp4[((0 * 4 + kt) * 4 + ntp) * 32];
#pragma unroll
                    for (int s = 0; s < 2; s++) {
                        mmaf16(d1s[s][2 * ntp][0], d1s[s][2 * ntp][1],
                            h0d[s][2 * kt][0], h0d[s][2 * kt][1],
                            h0d[s][2 * kt + 1][0], h0d[s][2 * kt + 1][1], u.x, u.y);
                        mmaf16(d1s[s][2 * ntp + 1][0], d1s[s][2 * ntp + 1][1],
                            h0d[s][2 * kt][0], h0d[s][2 * kt][1],
                            h0d[s][2 * kt + 1][0], h0d[s][2 * kt + 1][1], u.z, u.w);
                    }
                }
        }

        // ===== layer1 B: d2 += h0(t) @ Win1 =====
#pragma unroll
        for (int kt = 0; kt < 4; kt++)
#pragma unroll
            for (int ntp = 0; ntp < 4; ntp++) {
                uint4 u = wp4[((1 * 4 + kt) * 4 + ntp) * 32];
#pragma unroll
                for (int s = 0; s < 2; s++) {
                    mmaf16(d2s[s][2 * ntp][0], d2s[s][2 * ntp][1],
                        h0d[s][2 * kt][0], h0d[s][2 * kt][1],
                        h0d[s][2 * kt + 1][0], h0d[s][2 * kt + 1][1], u.x, u.y);
                    mmaf16(d2s[s][2 * ntp + 1][0], d2s[s][2 * ntp + 1][1],
                        h0d[s][2 * kt][0], h0d[s][2 * kt][1],
                        h0d[s][2 * kt + 1][0], h0d[s][2 * kt + 1][1], u.z, u.w);
                }
            }

        // ===== head(t-1) per stream, in the MMA shadow =====
        if (t > 0) {
#pragma unroll
            for (int s = 0; s < 2; s++)
#pragma unroll
                for (int h = 0; h < 2; h++) {
                    uint32_t za0 = 0u, za1 = 0u;
#pragma unroll
                    for (int nt = 0; nt < 8; nt++) {
                        uint32_t u = h1d[s][nt][h];
                        hfma2_acc(za0, u, wl2[nt][0]);
                        hfma2_acc(za1, u, wl2[nt][1]);
                    }
                    float2 f0 = __half22float2(*reinterpret_cast<__half2*>(&za0));
                    float2 f1 = __half22float2(*reinterpret_cast<__half2*>(&za1));
                    float z0 = f0.x + f0.y, z1 = f1.x + f1.y;
                    z0 += __shfl_xor_sync(0xffffffffu, z0, 1);
                    z0 += __shfl_xor_sync(0xffffffffu, z0, 2);
                    z1 += __shfl_xor_sync(0xffffffffu, z1, 1);
                    z1 += __shfl_xor_sync(0xffffffffu, z1, 2);
                    z0 += bl0; z1 += bl1;
                    int bit = (int)((xb[s][h] >> (t - 1)) & 1ull);
                    float mx = fmaxf(z0, z1);
                    float lse = mx + __logf(1.f + __expf(-fabsf(z0 - z1)));
                    float zsel = bit ? z1 : z0;
                    lp[s][h] += 0.5f * (zsel - lse);
                }
        }

        // ===== activations (in place on D) =====
#pragma unroll
        for (int s = 0; s < 2; s++)
#pragma unroll
            for (int nt = 0; nt < 8; nt++) {
                h1d[s][nt][0] = elu_h2(d2s[s][nt][0]);
                h1d[s][nt][1] = elu_h2(d2s[s][nt][1]);
            }
        if (!last) {
#pragma unroll
            for (int s = 0; s < 2; s++)
#pragma unroll
                for (int nt = 0; nt < 8; nt++) {
                    h0d[s][nt][0] = elu_h2(d1s[s][nt][0]);
                    h0d[s][nt][1] = elu_h2(d1s[s][nt][1]);
                }
        }
    }
    // h0d = h0(64), h1d = h1(64) per stream

    // ===== cavity head =====
#pragma unroll
    for (int s = 0; s < 2; s++)
#pragma unroll
        for (int h = 0; h < 2; h++) {
            float zc[8];
#pragma unroll
            for (int c = 0; c < 8; c++) zc[c] = 0.f;
#pragma unroll
            for (int nt = 0; nt < 8; nt++) {
                __half2 ha = *reinterpret_cast<const __half2*>(&h0d[s][nt][h]);
                __half2 hb = *reinterpret_cast<const __half2*>(&h1d[s][nt][h]);
                float v0 = __half2float(__low2half(ha));
                float v1 = __half2float(__high2half(ha));
                float w0 = __half2float(__low2half(hb));
                float w1 = __half2float(__high2half(hb));
                int col = 8 * nt + 2 * m;
#pragma unroll
                for (int c = 0; c < 8; c++) {
                    zc[c] += v0 * sCav[col][c] + v1 * sCav[col + 1][c]
                           + w0 * sCav[64 + col][c] + w1 * sCav[64 + col + 1][c];
                }
            }
#pragma unroll
            for (int c = 0; c < 8; c++) {
                zc[c] += __shfl_xor_sync(0xffffffffu, zc[c], 1);
                zc[c] += __shfl_xor_sync(0xffffffffu, zc[c], 2);
                zc[c] += sB[c];
            }
            float mx = zc[0];
#pragma unroll
            for (int c = 1; c < 8; c++) mx = fmaxf(mx, zc[c]);
            float ss = 0.f;
#pragma unroll
            for (int c = 0; c < 8; c++) ss += __expf(zc[c] - mx);
            float lse = mx + __logf(ss);
            float zsel = zc[0];
#pragma unroll
            for (int c = 1; c < 8; c++) if (xl[s][h] == c) zsel = zc[c];
            float total = lp[s][h] + 0.5f * (zsel - lse);
            if (m == 0)
                out[rowbase + 16 * s + q + 8 * h] = total;
        }
}

extern "C" void kernel_launch(void* const* d_in, const int* in_sizes, int n_in,
                              void* d_out, int out_size) {
    (void)in_sizes; (void)n_in; (void)out_size;
    const int*   x    = (const int*)d_in[0];
    const float* Win0 = (const float*)d_in[1];
    const float* Win1 = (const float*)d_in[2];
    const float* Wh   = (const float*)d_in[3];
    const float* b    = (const float*)d_in[4];
    const float* Wlat = (const float*)d_in[5];
    const float* blat = (const float*)d_in[6];
    const float* Wcav = (const float*)d_in[7];
    const float* bcav = (const float*)d_in[8];
    float* out = (float*)d_out;
    rnn_fused<<<128, 128>>>(x, Win0, Win1, Wh, b, Wlat, blat, Wcav, bcav, out);
}

// round 13
// speedup vs baseline: 1.4597x; 1.3296x over previous
#include <cuda_runtime.h>
#include <cuda_fp16.h>
#include <stdint.h>

// RNN1DGeneral: B=16384, L=64, H=64, DEPTH=2, D_L=2, D_C=8, LPF=0.5
// R13 = R9 + Win1 ALSO pinned in registers (128 regs of weights total),
// with all small constant tables (V, b1, Wlat) moved to SMEM broadcast
// loads so the register budget fits (~230 < 255; R8 spilled because it
// kept the tables in registers on top of the pins).

__device__ __forceinline__ void mmaf16(uint32_t& d0, uint32_t& d1,
    uint32_t a0, uint32_t a1, uint32_t a2, uint32_t a3,
    uint32_t b0, uint32_t b1)
{
    asm("mma.sync.aligned.m16n8k16.row.col.f16.f16.f16.f16 "
        "{%0,%1},{%2,%3,%4,%5},{%6,%7},{%0,%1};"
        : "+r"(d0), "+r"(d1)
        : "r"(a0), "r"(a1), "r"(a2), "r"(a3), "r"(b0), "r"(b1));
}

__device__ __forceinline__ void mmaf16_init(uint32_t& d0, uint32_t& d1,
    uint32_t a0, uint32_t a1, uint32_t a2, uint32_t a3,
    uint32_t b0, uint32_t b1, uint32_t c0, uint32_t c1)
{
    asm("mma.sync.aligned.m16n8k16.row.col.f16.f16.f16.f16 "
        "{%0,%1},{%2,%3,%4,%5},{%6,%7},{%8,%9};"
        : "=r"(d0), "=r"(d1)
        : "r"(a0), "r"(a1), "r"(a2), "r"(a3), "r"(b0), "r"(b1),
          "r"(c0), "r"(c1));
}

__device__ __forceinline__ uint32_t pack2(float lo, float hi) {
    __half2 h = __floats2half2_rn(lo, hi);
    return *reinterpret_cast<const uint32_t*>(&h);
}

__device__ __forceinline__ uint32_t elu_h2(uint32_t u) {
    const uint32_t LOG2E2 = 0x3DC53DC5u;
    const uint32_t ONE2   = 0x3C003C00u;
    uint32_t zero = 0u;
    uint32_t t, e, em1, mx, mn, r;
    asm("mul.rn.f16x2 %0, %1, %2;" : "=r"(t) : "r"(u), "r"(LOG2E2));
    asm("ex2.approx.f16x2 %0, %1;" : "=r"(e) : "r"(t));
    asm("sub.rn.f16x2 %0, %1, %2;" : "=r"(em1) : "r"(e), "r"(ONE2));
    asm("max.f16x2 %0, %1, %2;" : "=r"(mx) : "r"(u), "r"(zero));
    asm("min.f16x2 %0, %1, %2;" : "=r"(mn) : "r"(em1), "r"(zero));
    asm("add.rn.f16x2 %0, %1, %2;" : "=r"(r) : "r"(mx), "r"(mn));
    return r;
}

__device__ __forceinline__ void hfma2_acc(uint32_t& acc, uint32_t a, uint32_t b) {
    asm("fma.rn.f16x2 %0, %1, %2, %0;" : "+r"(acc) : "r"(a), "r"(b));
}

__global__ void __launch_bounds__(256, 1) rnn_fused(
    const int*   __restrict__ x,     // [16384, 65]
    const float* __restrict__ Win0,  // [2, 64]
    const float* __restrict__ Win1,  // [64, 64]
    const float* __restrict__ Wh,    // [2, 64, 64]
    const float* __restrict__ bvec,  // [2, 64]
    const float* __restrict__ Wlat,  // [64, 2]
    const float* __restrict__ blat,  // [2]
    const float* __restrict__ Wcav,  // [128, 8]
    const float* __restrict__ bcav,  // [8]
    float*       __restrict__ out)   // [16384]
{
    __shared__ uint4    sW4[3 * 4 * 4 * 32];  // l: 0=Wh0, 1=Win1, 2=Wh1 (24 KB)
    __shared__ uint32_t sVh[3 * 36];          // pack2(V[i][8nt+2m],+1) at i*36+4nt+m
    __shared__ uint32_t sB1h[32];             // pack2(b1[8g+2m],+1) at 4g+m
    __shared__ uint2    sWl2[32];             // Wlat pairs at 4g+m
    __shared__ float    sCav[128][8];
    __shared__ float    sB[10];               // [0..7]=bcav, [8..9]=blat

    const int tid = threadIdx.x;

    for (int i = tid; i < 3 * 4 * 4 * 32; i += 256) {
        int lane_ = i & 31, ntp_ = (i >> 5) & 3, kt_ = (i >> 7) & 3, l_ = i >> 9;
        int q_ = lane_ >> 2, m_ = lane_ & 3;
        int k0 = 16 * kt_ + 2 * m_;
        int n0 = 16 * ntp_ + q_;
        int n1 = n0 + 8;
        const float* src = (l_ == 0) ? Wh : (l_ == 1 ? Win1 : (Wh + 4096));
        uint4 u;
        u.x = pack2(src[k0 * 64 + n0],       src[(k0 + 1) * 64 + n0]);
        u.y = pack2(src[(k0 + 8) * 64 + n0], src[(k0 + 9) * 64 + n0]);
        u.z = pack2(src[k0 * 64 + n1],       src[(k0 + 1) * 64 + n1]);
        u.w = pack2(src[(k0 + 8) * 64 + n1], src[(k0 + 9) * 64 + n1]);
        sW4[i] = u;
    }
    for (int i = tid; i < 128 * 8; i += 256)
        (reinterpret_cast<float*>(sCav))[i] = Wcav[i];
    if (tid < 96) {
        int i = tid >> 5, idx = tid & 31;
        int nt_ = idx >> 2, mm = idx & 3;
        int c = 8 * nt_ + 2 * mm;
        float lo, hi;
        if (i == 2) { lo = bvec[c]; hi = bvec[c + 1]; }
        else { lo = Win0[64 * i + c] + bvec[c]; hi = Win0[64 * i + c + 1] + bvec[c + 1]; }
        sVh[i * 36 + idx] = pack2(lo, hi);
    }
    if (tid < 32) {
        int g = tid >> 2, mm = tid & 3;
        int col = 8 * g + 2 * mm;
        uint2 w;
        w.x = pack2(Wlat[2 * col],     Wlat[2 * col + 2]);
        w.y = pack2(Wlat[2 * col + 1], Wlat[2 * col + 3]);
        sWl2[tid] = w;
        sB1h[tid] = pack2(bvec[64 + col], bvec[64 + col + 1]);
    }
    if (tid < 8) sB[tid] = bcav[tid];
    if (tid < 2) sB[8 + tid] = blat[tid];
    __syncthreads();

    const int lane = tid & 31, warp = tid >> 5;
    const int q = lane >> 2, m = lane & 3;
    const int rowbase = blockIdx.x * 128 + warp * 16;
    const uint4* wp4 = sW4 + lane;

    // ---- pin Wh1 (l=2) and Win1 (l=1): 32 uint4 = 128 regs ----
    uint4 wH1[16], wIn1[16];
#pragma unroll
    for (int kt = 0; kt < 4; kt++)
#pragma unroll
        for (int ntp = 0; ntp < 4; ntp++) {
            wH1[kt * 4 + ntp]  = wp4[((2 * 4 + kt) * 4 + ntp) * 32];
            wIn1[kt * 4 + ntp] = wp4[((1 * 4 + kt) * 4 + ntp) * 32];
        }

    // pack per-row input bits; h in {0,1} -> row = rowbase + q + 8*h
    uint64_t xb[2];
    int xl[2];
#pragma unroll
    for (int rr = 0; rr < 2; rr++) {
        int r = rowbase + q + rr * 8;
        const int* xr = x + r * 65;
        uint64_t bits = 0;
#pragma unroll 8
        for (int t = 0; t < 64; t++)
            bits |= ((uint64_t)(xr[t] & 1)) << t;
        xb[rr] = bits;
        xl[rr] = xr[64] & 7;
    }

    const float bl0 = sB[8], bl1 = sB[9];

    // hidden state, packed post-ELU half2; h0(0)=elu(b0), h1(-1)=0
    uint32_t h0d[8][2], h1d[8][2];
#pragma unroll
    for (int nt = 0; nt < 8; nt++) {
        uint32_t v = elu_h2(sVh[2 * 36 + 4 * nt + m]);
        h0d[nt][0] = v; h0d[nt][1] = v;
        h1d[nt][0] = 0u; h1d[nt][1] = 0u;
    }

    float lp[2] = {0.f, 0.f};
    uint32_t d1s[8][2], d2s[8][2];

#pragma unroll 1
    for (int t = 0; t < 65; t++) {
        const bool last = (t == 64);

        // layer1 A: d2s = b1 + h1(t-1)@Wh1  (register weights, b1 from SMEM)
#pragma unroll
        for (int ntp = 0; ntp < 4; ntp++) {
            uint4 u = wH1[ntp];
            uint32_t c0 = sB1h[4 * (2 * ntp) + m];
            uint32_t c1 = sB1h[4 * (2 * ntp + 1) + m];
            mmaf16_init(d2s[2 * ntp][0], d2s[2 * ntp][1],
                h1d[0][0], h1d[0][1], h1d[1][0], h1d[1][1], u.x, u.y, c0, c0);
            mmaf16_init(d2s[2 * ntp + 1][0], d2s[2 * ntp + 1][1],
                h1d[0][0], h1d[0][1], h1d[1][0], h1d[1][1], u.z, u.w, c1, c1);
        }
#pragma unroll
        for (int kt = 1; kt < 4; kt++)
#pragma unroll
            for (int ntp = 0; ntp < 4; ntp++) {
                uint4 u = wH1[kt * 4 + ntp];
                mmaf16(d2s[2 * ntp][0], d2s[2 * ntp][1],
                    h1d[2 * kt][0], h1d[2 * kt][1],
                    h1d[2 * kt + 1][0], h1d[2 * kt + 1][1], u.x, u.y);
                mmaf16(d2s[2 * ntp + 1][0], d2s[2 * ntp + 1][1],
                    h1d[2 * kt][0], h1d[2 * kt][1],
                    h1d[2 * kt + 1][0], h1d[2 * kt + 1][1], u.z, u.w);
            }

        // layer0(next): d1s = V[x_t] + h0(t)@Wh0  (only remaining LDS.128)
        if (!last) {
            int i0 = (int)((xb[0] >> t) & 1ull);
            int i1 = (int)((xb[1] >> t) & 1ull);
#pragma unroll
            for (int ntp = 0; ntp < 4; ntp++) {
                uint4 u = wp4[((0 * 4 + 0) * 4 + ntp) * 32];
                int a0i = 2 * ntp, a1i = 2 * ntp + 1;
                uint32_t ca0 = sVh[i0 * 36 + 4 * a0i + m];
                uint32_t cb0 = sVh[i1 * 36 + 4 * a0i + m];
                uint32_t ca1 = sVh[i0 * 36 + 4 * a1i + m];
                uint32_t cb1 = sVh[i1 * 36 + 4 * a1i + m];
                mmaf16_init(d1s[a0i][0], d1s[a0i][1],
                    h0d[0][0], h0d[0][1], h0d[1][0], h0d[1][1], u.x, u.y, ca0, cb0);
                mmaf16_init(d1s[a1i][0], d1s[a1i][1],
                    h0d[0][0], h0d[0][1], h0d[1][0], h0d[1][1], u.z, u.w, ca1, cb1);
            }
#pragma unroll
            for (int kt = 1; kt < 4; kt++)
#pragma unroll
                for (int ntp = 0; ntp < 4; ntp++) {
                    uint4 u = wp4[((0 * 4 + kt) * 4 + ntp) * 32];
                    mmaf16(d1s[2 * ntp][0], d1s[2 * ntp][1],
                        h0d[2 * kt][0], h0d[2 * kt][1],
                        h0d[2 * kt + 1][0], h0d[2 * kt + 1][1], u.x, u.y);
                    mmaf16(d1s[2 * ntp + 1][0], d1s[2 * ntp + 1][1],
                        h0d[2 * kt][0], h0d[2 * kt][1],
                        h0d[2 * kt + 1][0], h0d[2 * kt + 1][1], u.z, u.w);
                }
        }

        // layer1 B: d2s += h0(t)@Win1  (register weights)
#pragma unroll
        for (int kt = 0; kt < 4; kt++)
#pragma unroll
            for (int ntp = 0; ntp < 4; ntp++) {
                uint4 u = wIn1[kt * 4 + ntp];
                mmaf16(d2s[2 * ntp][0], d2s[2 * ntp][1],
                    h0d[2 * kt][0], h0d[2 * kt][1],
                    h0d[2 * kt + 1][0], h0d[2 * kt + 1][1], u.x, u.y);
                mmaf16(d2s[2 * ntp + 1][0], d2s[2 * ntp + 1][1],
                    h0d[2 * kt][0], h0d[2 * kt][1],
                    h0d[2 * kt + 1][0], h0d[2 * kt + 1][1], u.z, u.w);
            }

        // head(t-1) from h1d = h1(t-1), in the MMA shadow
        if (t > 0) {
#pragma unroll
            for (int h = 0; h < 2; h++) {
                uint32_t za0 = 0u, za1 = 0u;
#pragma unroll
                for (int g = 0; g < 8; g++) {
                    uint32_t u = h1d[g][h];
                    uint2 w = sWl2[4 * g + m];
                    hfma2_acc(za0, u, w.x);
                    hfma2_acc(za1, u, w.y);
                }
                float2 f0 = __half22float2(*reinterpret_cast<__half2*>(&za0));
                float2 f1 = __half22float2(*reinterpret_cast<__half2*>(&za1));
                float z0 = f0.x + f0.y, z1 = f1.x + f1.y;
                z0 += __shfl_xor_sync(0xffffffffu, z0, 1);
                z0 += __shfl_xor_sync(0xffffffffu, z0, 2);
                z1 += __shfl_xor_sync(0xffffffffu, z1, 1);
                z1 += __shfl_xor_sync(0xffffffffu, z1, 2);
                z0 += bl0; z1 += bl1;
                int bit = (int)((xb[h] >> (t - 1)) & 1ull);
                float mx = fmaxf(z0, z1);
                float lse = mx + __logf(1.f + __expf(-fabsf(z0 - z1)));
                float zsel = bit ? z1 : z0;
                lp[h] += 0.5f * (zsel - lse);
            }
        }

        // activations (in place on D)
#pragma unroll
        for (int nt = 0; nt < 8; nt++) {
            h1d[nt][0] = elu_h2(d2s[nt][0]);
            h1d[nt][1] = elu_h2(d2s[nt][1]);
        }
        if (!last) {
#pragma unroll
            for (int nt = 0; nt < 8; nt++) {
                h0d[nt][0] = elu_h2(d1s[nt][0]);
                h0d[nt][1] = elu_h2(d1s[nt][1]);
            }
        }
    }
    // h0d = h0(64), h1d = h1(64)

    // cavity head
#pragma unroll
    for (int h = 0; h < 2; h++) {
        float zc[8];
#pragma unroll
        for (int c = 0; c < 8; c++) zc[c] = 0.f;
#pragma unroll
        for (int nt = 0; nt < 8; nt++) {
            __half2 ha = *reinterpret_cast<const __half2*>(&h0d[nt][h]);
            __half2 hb = *reinterpret_cast<const __half2*>(&h1d[nt][h]);
            float v0 = __half2float(__low2half(ha));
            float v1 = __half2float(__high2half(ha));
            float w0 = __half2float(__low2half(hb));
            float w1 = __half2float(__high2half(hb));
            int col = 8 * nt + 2 * m;
#pragma unroll
            for (int c = 0; c < 8; c++) {
                zc[c] += v0 * sCav[col][c] + v1 * sCav[col + 1][c]
                       + w0 * sCav[64 + col][c] + w1 * sCav[64 + col + 1][c];
            }
        }
#pragma unroll
        for (int c = 0; c < 8; c++) {
            zc[c] += __shfl_xor_sync(0xffffffffu, zc[c], 1);
            zc[c] += __shfl_xor_sync(0xffffffffu, zc[c], 2);
            zc[c] += sB[c];
        }
        float mx = zc[0];
#pragma unroll
        for (int c = 1; c < 8; c++) mx = fmaxf(mx, zc[c]);
        float s = 0.f;
#pragma unroll
        for (int c = 0; c < 8; c++) s += __expf(zc[c] - mx);
        float lse = mx + __logf(s);
        float zsel = zc[0];
#pragma unroll
        for (int c = 1; c < 8; c++) if (xl[h] == c) zsel = zc[c];
        float total = lp[h] + 0.5f * (zsel - lse);
        if (m == 0)
            out[rowbase + q + 8 * h] = total;
    }
}

extern "C" void kernel_launch(void* const* d_in, const int* in_sizes, int n_in,
                              void* d_out, int out_size) {
    (void)in_sizes; (void)n_in; (void)out_size;
    const int*   x    = (const int*)d_in[0];
    const float* Win0 = (const float*)d_in[1];
    const float* Win1 = (const float*)d_in[2];
    const float* Wh   = (const float*)d_in[3];
    const float* b    = (const float*)d_in[4];
    const float* Wlat = (const float*)d_in[5];
    const float* blat = (const float*)d_in[6];
    const float* Wcav = (const float*)d_in[7];
    const float* bcav = (const float*)d_in[8];
    float* out = (float*)d_out;
    rnn_fused<<<128, 256>>>(x, Win0, Win1, Wh, b, Wlat, blat, Wcav, bcav, out);
}